// round 4
// baseline (speedup 1.0000x reference)
#include <cuda_runtime.h>
#include <cuda_bf16.h>
#include <cstdint>

// MaxUnpooling2D via L2-phased scatter-add (single persistent kernel).
// updates: [16,128,128,64] f32   d_in[0]
// mask:    [16,128,128,64] int32 d_in[1], values in [0, 256*256*64)
// out:     [16,256,256,64] f32   (256 MB)
// out[b*OUT_FLAT + mask[i]] += updates[i]
//
// Strategy: 8 phases x 2 batches. Per phase: zero the 32MB output window
// (write-allocates into L2), device-wide barrier, scatter the phase's 2M
// updates (atomics hit L2-resident zeroed lines). Write-back happens once.

static constexpr int N_IN            = 1 << 24;        // 16,777,216
static constexpr int OUT_FLAT        = 1 << 22;        // 4,194,304 floats/batch
static constexpr int NBATCH          = 16;
static constexpr int BATCH_PER_PHASE = 2;
static constexpr int NPHASE          = NBATCH / BATCH_PER_PHASE;     // 8
static constexpr int ELEMS_PER_PHASE = BATCH_PER_PHASE << 20;        // 2M elems
static constexpr int OUT_PER_PHASE   = BATCH_PER_PHASE * OUT_FLAT;   // 8M floats

__device__ unsigned int g_bar[NPHASE];   // ticket counters; never reset (wrap-safe)

__device__ __forceinline__ void grid_barrier(unsigned int* bar, unsigned int nctas) {
    __syncthreads();
    if (threadIdx.x == 0) {
        __threadfence();                         // make this CTA's stores visible
        unsigned int v = atomicAdd(bar, 1u);     // my ticket
        unsigned int target = v - (v % nctas) + nctas;  // next multiple of nctas
        volatile unsigned int* p = (volatile unsigned int*)bar;
        while ((int)(*p - target) < 0) { __nanosleep(64); }
    }
    __syncthreads();
}

__global__ __launch_bounds__(256, 8)
void unpool_phased_kernel(const float4* __restrict__ updates4,
                          const int4*   __restrict__ mask4,
                          float*        __restrict__ out,
                          unsigned int  nctas) {
    const int tid      = blockIdx.x * blockDim.x + threadIdx.x;
    const int nthreads = gridDim.x * blockDim.x;

    for (int p = 0; p < NPHASE; p++) {
        // ---- Zero this phase's output window (32 MB -> resident in L2) ----
        {
            float4* w = (float4*)(out + (long long)p * OUT_PER_PHASE);
            const int n4 = OUT_PER_PHASE / 4;            // 2M float4
            const float4 z = make_float4(0.f, 0.f, 0.f, 0.f);
            for (int i = tid; i < n4; i += nthreads) w[i] = z;
        }

        grid_barrier(&g_bar[p], nctas);

        // ---- Scatter this phase's updates into the L2-resident window ----
        {
            const int base4 = p * (ELEMS_PER_PHASE / 4); // first float4-group
            const int n4    = ELEMS_PER_PHASE / 4;       // 512K groups
            for (int i = tid; i < n4; i += nthreads) {
                const int g = base4 + i;
                // 4 consecutive elems share a batch (1<<20 elems/batch, /4 ok)
                const int batch = (g * 4) >> 20;
                float* outb = out + (long long)batch * OUT_FLAT;

                float4 u = updates4[g];
                int4   m = mask4[g];
                if ((unsigned)m.x < (unsigned)OUT_FLAT) atomicAdd(outb + m.x, u.x);
                if ((unsigned)m.y < (unsigned)OUT_FLAT) atomicAdd(outb + m.y, u.y);
                if ((unsigned)m.z < (unsigned)OUT_FLAT) atomicAdd(outb + m.z, u.z);
                if ((unsigned)m.w < (unsigned)OUT_FLAT) atomicAdd(outb + m.w, u.w);
            }
        }
        // No barrier needed before next phase: next zero touches a disjoint
        // output window, and input reads are read-only.
    }
}

extern "C" void kernel_launch(void* const* d_in, const int* in_sizes, int n_in,
                              void* d_out, int out_size) {
    const float4* updates4 = (const float4*)d_in[0];
    const int4*   mask4    = (const int4*)d_in[1];
    float*        out      = (float*)d_out;

    // All CTAs must be co-resident for the spin barrier: size grid from
    // the occupancy query (no stream ops; capture-safe).
    int dev = 0;
    cudaGetDevice(&dev);
    int sms = 0;
    cudaDeviceGetAttribute(&sms, cudaDevAttrMultiProcessorCount, dev);
    int maxB = 0;
    cudaOccupancyMaxActiveBlocksPerMultiprocessor(&maxB, unpool_phased_kernel, 256, 0);
    if (maxB < 1) maxB = 1;
    unsigned int nctas = (unsigned int)(sms * maxB);     // 148*8 = 1184 expected

    unpool_phased_kernel<<<nctas, 256>>>(updates4, mask4, out, nctas);
}